// round 1
// baseline (speedup 1.0000x reference)
#include <cuda_runtime.h>
#include <math.h>

#define BATCH  4096
#define NMODES 512
#define NLU    128
#define NB     16
#define JB     16

// ---------------- scratch (static device globals; no allocation) ----------------
__device__ int   g_idx[BATCH * 256];   // per batch: 128 up indices, then 128 dn indices
__device__ float g_logj[BATCH];
__device__ float g_sign[BATCH * 2];    // [2b+spin]
__device__ float g_labs[BATCH * 2];

// ---------------- kernel 1: occupied-index extraction (stable ascending) --------
__global__ void idx_kernel(const int* __restrict__ n) {
    int b = blockIdx.x;
    int t = threadIdx.x;                 // 256 threads, one site per thread per sector
    __shared__ int wcu[8], wcd[8];
    int vu = n[b * NMODES + t];
    int vd = n[b * NMODES + 256 + t];
    unsigned mu = __ballot_sync(0xffffffffu, vu != 0);
    unsigned md = __ballot_sync(0xffffffffu, vd != 0);
    int lane = t & 31, w = t >> 5;
    if (lane == 0) { wcu[w] = __popc(mu); wcd[w] = __popc(md); }
    __syncthreads();
    int bu = 0, bd = 0;
    for (int i = 0; i < w; i++) { bu += wcu[i]; bd += wcd[i]; }
    unsigned lt = (1u << lane) - 1u;
    if (vu) g_idx[b * 256 + bu + __popc(mu & lt)] = t;
    if (vd) g_idx[b * 256 + 128 + bd + __popc(md & lt)] = t;
}

// ---------------- kernel 2: Jastrow  log_j = -0.5 * n V n ----------------------
__global__ __launch_bounds__(256) void jastrow_kernel(const int* __restrict__ n,
                                                      const float* __restrict__ v) {
    int b0 = blockIdx.x * JB;
    __shared__ float sn[JB][NMODES];
    __shared__ float spart[JB][8];
    int tid = threadIdx.x;
    for (int x = tid; x < JB * NMODES; x += 256)
        sn[x >> 9][x & 511] = (float)n[b0 * NMODES + x];
    __syncthreads();

    int j0 = tid * 2;
    float acc0[JB], acc1[JB];
#pragma unroll
    for (int bb = 0; bb < JB; bb++) { acc0[bb] = 0.f; acc1[bb] = 0.f; }

    for (int i = 0; i < NMODES; i++) {
        float2 vv = *reinterpret_cast<const float2*>(v + (size_t)i * NMODES + j0);
#pragma unroll
        for (int bb = 0; bb < JB; bb++) {
            float f = sn[bb][i];
            acc0[bb] += f * vv.x;
            acc1[bb] += f * vv.y;
        }
    }

    int lane = tid & 31, wrp = tid >> 5;
#pragma unroll
    for (int bb = 0; bb < JB; bb++) {
        float s = acc0[bb] * sn[bb][j0] + acc1[bb] * sn[bb][j0 + 1];
#pragma unroll
        for (int off = 16; off > 0; off >>= 1)
            s += __shfl_down_sync(0xffffffffu, s, off);
        if (lane == 0) spart[bb][wrp] = s;
    }
    __syncthreads();
    if (tid < JB) {
        float s = 0.f;
#pragma unroll
        for (int w = 0; w < 8; w++) s += spart[tid][w];
        g_logj[b0 + tid] = -0.5f * s;
    }
}

// ---------------- kernel 3: blocked LU (partial pivot) -> slogdet ---------------
extern __shared__ float As[];
#define A(i, j) As[(i) * 129 + (j)]

__global__ __launch_bounds__(256, 3) void lu_kernel(const float* __restrict__ phi_up,
                                                    const float* __restrict__ phi_dn) {
    int cta  = blockIdx.x;          // 0..8191
    int b    = cta >> 1;
    int spin = cta & 1;
    const float* __restrict__ phi = spin ? phi_dn : phi_up;
    const int*   __restrict__ idx = g_idx + b * 256 + spin * 128;

    __shared__ float s_red[4];
    __shared__ int   s_ridx[4];
    __shared__ int   s_p;
    __shared__ float s_piv;

    int tid  = threadIdx.x;
    int lane = tid & 31, wrp = tid >> 5;

    // gather M = phi[idx] into smem (coalesced: 2 rows per iteration)
    int c = tid & 127, rh = tid >> 7;
    for (int it = 0; it < 64; it++) {
        int r = (it << 1) + rh;
        A(r, c) = phi[idx[r] * NLU + c];
    }
    __syncthreads();

    float t_logabs = 0.f;
    float t_sign   = 1.f;

    int tx = tid & 15, ty = tid >> 4;

    for (int k0 = 0; k0 < NLU; k0 += NB) {
        // ---------------- panel factorization (cols k0..k0+NB-1) ----------------
        for (int kk = 0; kk < NB; kk++) {
            int k = k0 + kk;
            // pivot search on column k, rows k..127 (warps 0..3)
            float pv = -1.f; int pvi = k;
            if (tid < NLU && tid >= k) { pv = fabsf(A(tid, k)); pvi = tid; }
#pragma unroll
            for (int off = 16; off > 0; off >>= 1) {
                float ov = __shfl_down_sync(0xffffffffu, pv, off);
                int   oi = __shfl_down_sync(0xffffffffu, pvi, off);
                if (ov > pv) { pv = ov; pvi = oi; }
            }
            if (tid < NLU && lane == 0) { s_red[wrp] = pv; s_ridx[wrp] = pvi; }
            __syncthreads();
            if (tid == 0) {
                float bv = s_red[0]; int bi = s_ridx[0];
                for (int w = 1; w < 4; w++)
                    if (s_red[w] > bv) { bv = s_red[w]; bi = s_ridx[w]; }
                s_p = bi;
                float pivv = A(bi, k);
                s_piv = pivv;
                t_logabs += logf(fabsf(pivv));
                if (pivv < 0.f) t_sign = -t_sign;
                if (bi != k)    t_sign = -t_sign;
            }
            __syncthreads();
            int p = s_p;
            float piv = s_piv;
            if (p != k && tid < NLU) {   // full-width row swap
                float tmp = A(k, tid); A(k, tid) = A(p, tid); A(p, tid) = tmp;
            }
            __syncthreads();
            float invp = 1.0f / piv;
            if (tid < NLU && tid > k) A(tid, k) *= invp;   // multipliers (L column)
            __syncthreads();
            // rank-1 update restricted to panel columns j in (k, k0+NB)
            int j = k0 + tx;
            if (j > k) {
                float ukj = A(k, j);
                for (int i = k + 1 + ty; i < NLU; i += 16)
                    A(i, j) -= A(i, k) * ukj;
            }
            __syncthreads();
        }

        int base = k0 + NB;
        int m = NLU - base;
        if (m > 0) {
            // ---------------- TRSM: U12 = L11^{-1} * A12 ------------------------
            for (int j = base + tid; j < NLU; j += 256) {
                float u[NB];
#pragma unroll
                for (int rr = 0; rr < NB; rr++) {
                    float x = A(k0 + rr, j);
#pragma unroll
                    for (int t = 0; t < NB; t++)
                        if (t < rr) x -= A(k0 + rr, k0 + t) * u[t];
                    u[rr] = x;
                    A(k0 + rr, j) = x;
                }
            }
            __syncthreads();

            // ---------------- trailing GEMM: A22 -= L21 * U12 -------------------
            for (int sa = 0; sa < m; sa += 64)
            for (int sb = 0; sb < m; sb += 64) {
                int ia[4], jb[4];
                bool rok[4], cok[4];
#pragma unroll
                for (int a = 0; a < 4; a++) {
                    int i = base + sa + ty + 16 * a;
                    rok[a] = (i < NLU); ia[a] = rok[a] ? i : (NLU - 1);
                    int jj = base + sb + tx + 16 * a;
                    cok[a] = (jj < NLU); jb[a] = cok[a] ? jj : (NLU - 1);
                }
                float acc[4][4];
#pragma unroll
                for (int a = 0; a < 4; a++)
#pragma unroll
                for (int q = 0; q < 4; q++)
                    acc[a][q] = A(ia[a], jb[q]);
#pragma unroll
                for (int t = 0; t < NB; t++) {
                    float la[4], lb[4];
#pragma unroll
                    for (int a = 0; a < 4; a++) {
                        la[a] = A(ia[a], k0 + t);
                        lb[a] = A(k0 + t, jb[a]);
                    }
#pragma unroll
                    for (int a = 0; a < 4; a++)
#pragma unroll
                    for (int q = 0; q < 4; q++)
                        acc[a][q] -= la[a] * lb[q];
                }
#pragma unroll
                for (int a = 0; a < 4; a++)
#pragma unroll
                for (int q = 0; q < 4; q++)
                    if (rok[a] && cok[q]) A(ia[a], jb[q]) = acc[a][q];
            }
        }
        __syncthreads();
    }

    if (tid == 0) {
        g_sign[cta] = t_sign;
        g_labs[cta] = t_logabs;
    }
}

// ---------------- kernel 4: combine ---------------------------------------------
__global__ void combine_kernel(float* __restrict__ out) {
    int b = blockIdx.x * 256 + threadIdx.x;
    if (b < BATCH) {
        out[b]         = g_sign[2 * b] * g_sign[2 * b + 1];
        out[BATCH + b] = g_logj[b] + g_labs[2 * b] + g_labs[2 * b + 1];
    }
}

// ---------------- launch ---------------------------------------------------------
extern "C" void kernel_launch(void* const* d_in, const int* in_sizes, int n_in,
                              void* d_out, int out_size) {
    const int*   n      = (const int*)d_in[0];
    const float* phi_up = (const float*)d_in[1];
    const float* phi_dn = (const float*)d_in[2];
    const float* v      = (const float*)d_in[3];
    float* out = (float*)d_out;

    const int LU_SMEM = NLU * 129 * (int)sizeof(float);   // 66048 B
    cudaFuncSetAttribute(lu_kernel, cudaFuncAttributeMaxDynamicSharedMemorySize, LU_SMEM);

    idx_kernel<<<BATCH, 256>>>(n);
    jastrow_kernel<<<BATCH / JB, 256>>>(n, v);
    lu_kernel<<<BATCH * 2, 256, LU_SMEM>>>(phi_up, phi_dn);
    combine_kernel<<<(BATCH + 255) / 256, 256>>>(out);
}

// round 2
// speedup vs baseline: 1.3337x; 1.3337x over previous
#include <cuda_runtime.h>
#include <math.h>

#define BATCH  4096
#define NMODES 512
#define NLU    128
#define NB     16
#define JB     16

// ---------------- scratch (static device globals; no allocation) ----------------
__device__ int   g_idx[BATCH * 256];   // per batch: 128 up indices, then 128 dn indices
__device__ float g_logj[BATCH];
__device__ float g_sign[BATCH * 2];    // [2b+spin]
__device__ float g_labs[BATCH * 2];

// ---------------- kernel 1: occupied-index extraction (stable ascending) --------
__global__ void idx_kernel(const int* __restrict__ n) {
    int b = blockIdx.x;
    int t = threadIdx.x;                 // 256 threads, one site per thread per sector
    __shared__ int wcu[8], wcd[8];
    int vu = n[b * NMODES + t];
    int vd = n[b * NMODES + 256 + t];
    unsigned mu = __ballot_sync(0xffffffffu, vu != 0);
    unsigned md = __ballot_sync(0xffffffffu, vd != 0);
    int lane = t & 31, w = t >> 5;
    if (lane == 0) { wcu[w] = __popc(mu); wcd[w] = __popc(md); }
    __syncthreads();
    int bu = 0, bd = 0;
    for (int i = 0; i < w; i++) { bu += wcu[i]; bd += wcd[i]; }
    unsigned lt = (1u << lane) - 1u;
    if (vu) g_idx[b * 256 + bu + __popc(mu & lt)] = t;
    if (vd) g_idx[b * 256 + 128 + bd + __popc(md & lt)] = t;
}

// ---------------- kernel 2: Jastrow  log_j = -0.5 * n V n ----------------------
__global__ __launch_bounds__(256) void jastrow_kernel(const int* __restrict__ n,
                                                      const float* __restrict__ v) {
    int b0 = blockIdx.x * JB;
    __shared__ float sn[JB][NMODES];
    __shared__ float spart[JB][8];
    int tid = threadIdx.x;
    for (int x = tid; x < JB * NMODES; x += 256)
        sn[x >> 9][x & 511] = (float)n[b0 * NMODES + x];
    __syncthreads();

    int j0 = tid * 2;
    float acc0[JB], acc1[JB];
#pragma unroll
    for (int bb = 0; bb < JB; bb++) { acc0[bb] = 0.f; acc1[bb] = 0.f; }

    for (int i = 0; i < NMODES; i++) {
        float2 vv = *reinterpret_cast<const float2*>(v + (size_t)i * NMODES + j0);
#pragma unroll
        for (int bb = 0; bb < JB; bb++) {
            float f = sn[bb][i];
            acc0[bb] += f * vv.x;
            acc1[bb] += f * vv.y;
        }
    }

    int lane = tid & 31, wrp = tid >> 5;
#pragma unroll
    for (int bb = 0; bb < JB; bb++) {
        float s = acc0[bb] * sn[bb][j0] + acc1[bb] * sn[bb][j0 + 1];
#pragma unroll
        for (int off = 16; off > 0; off >>= 1)
            s += __shfl_down_sync(0xffffffffu, s, off);
        if (lane == 0) spart[bb][wrp] = s;
    }
    __syncthreads();
    if (tid < JB) {
        float s = 0.f;
#pragma unroll
        for (int w = 0; w < 8; w++) s += spart[tid][w];
        g_logj[b0 + tid] = -0.5f * s;
    }
}

// ---------------- kernel 3: blocked LU (partial pivot) -> slogdet ---------------
extern __shared__ float As[];
#define A(i, j) As[(i) * 129 + (j)]

__global__ __launch_bounds__(256, 3) void lu_kernel(const float* __restrict__ phi_up,
                                                    const float* __restrict__ phi_dn) {
    int cta  = blockIdx.x;          // 0..8191
    int b    = cta >> 1;
    int spin = cta & 1;
    const float* __restrict__ phi = spin ? phi_dn : phi_up;
    const int*   __restrict__ idx = g_idx + b * 256 + spin * 128;

    __shared__ int   s_pivlist[NB];
    __shared__ float s_acc[2];      // logabs, sign (written by warp0 lane0 at end)

    int tid  = threadIdx.x;
    int lane = tid & 31;

    // gather M = phi[idx] into smem (coalesced: 2 rows per iteration)
    {
        int c = tid & 127, rh = tid >> 7;
        for (int it = 0; it < 64; it++) {
            int r = (it << 1) + rh;
            A(r, c) = phi[idx[r] * NLU + c];
        }
    }

    float t_logabs = 0.f;
    float t_sign   = 1.f;

    int tx = tid & 15, ty = tid >> 4;

    for (int k0 = 0; k0 < NLU; k0 += NB) {
        __syncthreads();   // trailing matrix (incl. this panel) up to date

        // ========== single-warp panel factorization (warp 0, no block syncs) =====
        if (tid < 32) {
            int m0 = NLU - k0;     // panel rows
#pragma unroll
            for (int kk = 0; kk < NB; kk++) {
                int kabs = k0 + kk;
                // ---- pivot search: monotone key = (|v| bits & ~0x7F) | rel_row
                unsigned best = 0u;
#pragma unroll
                for (int s = 0; s < 4; s++) {
                    int r = lane + 32 * s;
                    if (r >= kk && r < m0) {
                        float v = A(k0 + r, kabs);
                        unsigned ab = __float_as_uint(v) & 0x7FFFFFFFu;
                        unsigned key = (ab & 0xFFFFFF80u) | (unsigned)r;
                        if (key > best) best = key;
                    }
                }
                best = __reduce_max_sync(0xffffffffu, best);
                int pr   = (int)(best & 0x7Fu);  // relative row
                int pabs = k0 + pr;
                float pivv = A(pabs, kabs);      // broadcast read (pre-swap value)
                t_logabs += __logf(fabsf(pivv));
                if (pivv < 0.f) t_sign = -t_sign;
                if (lane == 0) s_pivlist[kk] = pabs;
                __syncwarp();
                if (pr != kk) {
                    t_sign = -t_sign;
                    if (lane < NB) {             // swap panel rows kk <-> pr (all 16 cols)
                        int cj = k0 + lane;
                        float a0 = A(kabs, cj), b0 = A(pabs, cj);
                        A(kabs, cj) = b0; A(pabs, cj) = a0;
                    }
                }
                __syncwarp();
                // ---- scale column kk, cache multipliers
                float inv = 1.0f / pivv;
                float lm[4]; int ra[4]; bool act[4];
#pragma unroll
                for (int s = 0; s < 4; s++) {
                    int r = lane + 32 * s;
                    act[s] = (r > kk && r < m0);
                    ra[s]  = k0 + r;
                    float mlt = act[s] ? A(ra[s], kabs) * inv : 0.f;
                    if (act[s]) A(ra[s], kabs) = mlt;
                    lm[s] = mlt;
                }
                // ---- rank-1 update on remaining panel columns
#pragma unroll
                for (int j = kk + 1; j < NB; j++) {
                    int cj = k0 + j;
                    float u = A(kabs, cj);       // pivot row value (post-swap)
#pragma unroll
                    for (int s = 0; s < 4; s++)
                        if (act[s]) A(ra[s], cj) -= lm[s] * u;
                }
                __syncwarp();
            }
        }
        __syncthreads();   // panel + pivot list visible to all warps

        int base = k0 + NB;
        int m = NLU - base;

        // ========== apply the 16 row swaps to trailing columns only ==============
        // (columns < k0 are dead for slogdet; skip them)
        for (int j = base + tid; j < NLU; j += 256) {
            for (int k = 0; k < NB; k++) {
                int p = s_pivlist[k];
                int kr = k0 + k;
                if (p != kr) {
                    float a0 = A(kr, j), b0 = A(p, j);
                    A(kr, j) = b0; A(p, j) = a0;
                }
            }
        }
        __syncthreads();

        if (m > 0) {
            // ---------------- TRSM: U12 = L11^{-1} * A12 ------------------------
            for (int j = base + tid; j < NLU; j += 256) {
                float u[NB];
#pragma unroll
                for (int rr = 0; rr < NB; rr++) {
                    float x = A(k0 + rr, j);
#pragma unroll
                    for (int t = 0; t < NB; t++)
                        if (t < rr) x -= A(k0 + rr, k0 + t) * u[t];
                    u[rr] = x;
                    A(k0 + rr, j) = x;
                }
            }
            __syncthreads();

            // ---------------- trailing GEMM: A22 -= L21 * U12 -------------------
            for (int sa = 0; sa < m; sa += 64)
            for (int sb = 0; sb < m; sb += 64) {
                int ia[4], jb[4];
                bool rok[4], cok[4];
#pragma unroll
                for (int a = 0; a < 4; a++) {
                    int i = base + sa + ty + 16 * a;
                    rok[a] = (i < NLU); ia[a] = rok[a] ? i : (NLU - 1);
                    int jj = base + sb + tx + 16 * a;
                    cok[a] = (jj < NLU); jb[a] = cok[a] ? jj : (NLU - 1);
                }
                float acc[4][4];
#pragma unroll
                for (int a = 0; a < 4; a++)
#pragma unroll
                for (int q = 0; q < 4; q++)
                    acc[a][q] = A(ia[a], jb[q]);
#pragma unroll
                for (int t = 0; t < NB; t++) {
                    float la[4], lb[4];
#pragma unroll
                    for (int a = 0; a < 4; a++) {
                        la[a] = A(ia[a], k0 + t);
                        lb[a] = A(k0 + t, jb[a]);
                    }
#pragma unroll
                    for (int a = 0; a < 4; a++)
#pragma unroll
                    for (int q = 0; q < 4; q++)
                        acc[a][q] -= la[a] * lb[q];
                }
#pragma unroll
                for (int a = 0; a < 4; a++)
#pragma unroll
                for (int q = 0; q < 4; q++)
                    if (rok[a] && cok[q]) A(ia[a], jb[q]) = acc[a][q];
            }
        }
    }

    if (tid == 0) {
        g_sign[cta] = t_sign;
        g_labs[cta] = t_logabs;
    }
    (void)s_acc;
}

// ---------------- kernel 4: combine ---------------------------------------------
__global__ void combine_kernel(float* __restrict__ out) {
    int b = blockIdx.x * 256 + threadIdx.x;
    if (b < BATCH) {
        out[b]         = g_sign[2 * b] * g_sign[2 * b + 1];
        out[BATCH + b] = g_logj[b] + g_labs[2 * b] + g_labs[2 * b + 1];
    }
}

// ---------------- launch ---------------------------------------------------------
extern "C" void kernel_launch(void* const* d_in, const int* in_sizes, int n_in,
                              void* d_out, int out_size) {
    const int*   n      = (const int*)d_in[0];
    const float* phi_up = (const float*)d_in[1];
    const float* phi_dn = (const float*)d_in[2];
    const float* v      = (const float*)d_in[3];
    float* out = (float*)d_out;

    const int LU_SMEM = NLU * 129 * (int)sizeof(float);   // 66048 B
    cudaFuncSetAttribute(lu_kernel, cudaFuncAttributeMaxDynamicSharedMemorySize, LU_SMEM);

    idx_kernel<<<BATCH, 256>>>(n);
    jastrow_kernel<<<BATCH / JB, 256>>>(n, v);
    lu_kernel<<<BATCH * 2, 256, LU_SMEM>>>(phi_up, phi_dn);
    combine_kernel<<<(BATCH + 255) / 256, 256>>>(out);
}

// round 3
// speedup vs baseline: 1.4765x; 1.1071x over previous
#include <cuda_runtime.h>
#include <math.h>

#define BATCH  4096
#define NMODES 512
#define NLU    128
#define NB     8
#define JB     16

// ---------------- scratch (static device globals; no allocation) ----------------
__device__ int   g_idx[BATCH * 256];   // per batch: 128 up indices, then 128 dn indices
__device__ float g_logj[BATCH];
__device__ float g_sign[BATCH * 2];    // [2b+spin]
__device__ float g_labs[BATCH * 2];

// ---------------- kernel 1: occupied-index extraction (stable ascending) --------
__global__ void idx_kernel(const int* __restrict__ n) {
    int b = blockIdx.x;
    int t = threadIdx.x;
    __shared__ int wcu[8], wcd[8];
    int vu = n[b * NMODES + t];
    int vd = n[b * NMODES + 256 + t];
    unsigned mu = __ballot_sync(0xffffffffu, vu != 0);
    unsigned md = __ballot_sync(0xffffffffu, vd != 0);
    int lane = t & 31, w = t >> 5;
    if (lane == 0) { wcu[w] = __popc(mu); wcd[w] = __popc(md); }
    __syncthreads();
    int bu = 0, bd = 0;
    for (int i = 0; i < w; i++) { bu += wcu[i]; bd += wcd[i]; }
    unsigned lt = (1u << lane) - 1u;
    if (vu) g_idx[b * 256 + bu + __popc(mu & lt)] = t;
    if (vd) g_idx[b * 256 + 128 + bd + __popc(md & lt)] = t;
}

// ---------------- kernel 2: Jastrow  log_j = -0.5 * n V n ----------------------
__global__ __launch_bounds__(256) void jastrow_kernel(const int* __restrict__ n,
                                                      const float* __restrict__ v) {
    int b0 = blockIdx.x * JB;
    __shared__ float sn[JB][NMODES];
    __shared__ float spart[JB][8];
    int tid = threadIdx.x;
    for (int x = tid; x < JB * NMODES; x += 256)
        sn[x >> 9][x & 511] = (float)n[b0 * NMODES + x];
    __syncthreads();

    int j0 = tid * 2;
    float acc0[JB], acc1[JB];
#pragma unroll
    for (int bb = 0; bb < JB; bb++) { acc0[bb] = 0.f; acc1[bb] = 0.f; }

    for (int i = 0; i < NMODES; i++) {
        float2 vv = *reinterpret_cast<const float2*>(v + (size_t)i * NMODES + j0);
#pragma unroll
        for (int bb = 0; bb < JB; bb++) {
            float f = sn[bb][i];
            acc0[bb] += f * vv.x;
            acc1[bb] += f * vv.y;
        }
    }

    int lane = tid & 31, wrp = tid >> 5;
#pragma unroll
    for (int bb = 0; bb < JB; bb++) {
        float s = acc0[bb] * sn[bb][j0] + acc1[bb] * sn[bb][j0 + 1];
#pragma unroll
        for (int off = 16; off > 0; off >>= 1)
            s += __shfl_down_sync(0xffffffffu, s, off);
        if (lane == 0) spart[bb][wrp] = s;
    }
    __syncthreads();
    if (tid < JB) {
        float s = 0.f;
#pragma unroll
        for (int w = 0; w < 8; w++) s += spart[tid][w];
        g_logj[b0 + tid] = -0.5f * s;
    }
}

// ---------------- kernel 3: blocked LU (partial pivot) -> slogdet ---------------
extern __shared__ float As[];
#define A(i, j) As[(i) * 129 + (j)]

__global__ __launch_bounds__(256, 3) void lu_kernel(const float* __restrict__ phi_up,
                                                    const float* __restrict__ phi_dn) {
    int cta  = blockIdx.x;          // 0..8191
    int b    = cta >> 1;
    int spin = cta & 1;
    const float* __restrict__ phi = spin ? phi_dn : phi_up;
    const int*   __restrict__ idx = g_idx + b * 256 + spin * 128;

    __shared__ int s_pivlist[NB];

    int tid  = threadIdx.x;
    int lane = tid & 31;

    // gather M = phi[idx] into smem (coalesced: 2 rows per iteration)
    {
        int c = tid & 127, rh = tid >> 7;
        for (int it = 0; it < 64; it++) {
            int r = (it << 1) + rh;
            A(r, c) = phi[idx[r] * NLU + c];
        }
    }

    float t_logabs = 0.f;
    float t_sign   = 1.f;

    int tx = tid & 15, ty = tid >> 4;

    for (int k0 = 0; k0 < NLU; k0 += NB) {
        __syncthreads();   // trailing matrix (incl. this panel) up to date

        // ===== single-warp REGISTER panel factorization (warp 0, no smem inside) ==
        if (tid < 32) {
            float p[4][NB];
            int   pos[4];
            bool  done[4];
#pragma unroll
            for (int s = 0; s < 4; s++) {
                int r = lane + 32 * s;
#pragma unroll
                for (int c = 0; c < NB; c++) p[s][c] = A(r, k0 + c);
                pos[s]  = r;
                done[s] = (r < k0);
            }

#pragma unroll
            for (int kk = 0; kk < NB; kk++) {
                int kabs = k0 + kk;
                // ---- pivot search: monotone key = (|v| bits & ~0x7F) | row
                unsigned best = 0u;
#pragma unroll
                for (int s = 0; s < 4; s++) {
                    if (!done[s]) {
                        unsigned ab  = __float_as_uint(p[s][kk]) & 0x7FFFFFFFu;
                        unsigned key = (ab & 0xFFFFFF80u) | (unsigned)(lane + 32 * s);
                        if (key > best) best = key;
                    }
                }
                best = __reduce_max_sync(0xffffffffu, best);
                int pabs = (int)(best & 0x7Fu);
                int psl  = pabs >> 5, pln = pabs & 31;

                // ---- broadcast pivot row (cols kk..NB-1) and its position
                float ur[NB];
#pragma unroll
                for (int c = kk; c < NB; c++) {
                    float t = (psl == 0) ? p[0][c] : (psl == 1) ? p[1][c]
                             : (psl == 2) ? p[2][c] : p[3][c];
                    ur[c] = __shfl_sync(0xffffffffu, t, pln);
                }
                int tq = (psl == 0) ? pos[0] : (psl == 1) ? pos[1]
                        : (psl == 2) ? pos[2] : pos[3];
                int qp = __shfl_sync(0xffffffffu, tq, pln);

                float piv = ur[kk];
                t_logabs += __logf(fabsf(piv));
                if (piv < 0.f)  t_sign = -t_sign;
                if (qp != kabs) t_sign = -t_sign;
                if (lane == 0)  s_pivlist[kk] = qp;

                // ---- virtual swap bookkeeping
#pragma unroll
                for (int s = 0; s < 4; s++) {
                    int r = lane + 32 * s;
                    if (r == pabs) { pos[s] = kabs; done[s] = true; }
                    else if (!done[s] && pos[s] == kabs) pos[s] = qp;
                }

                // ---- scale + rank-1 update (registers only)
                float inv = 1.0f / piv;
#pragma unroll
                for (int s = 0; s < 4; s++) {
                    if (!done[s]) {
                        float m = p[s][kk] * inv;
                        p[s][kk] = m;
#pragma unroll
                        for (int c = kk + 1; c < NB; c++)
                            p[s][c] -= m * ur[c];
                    }
                }
            }

            // ---- writeback to final (post-swap) positions
#pragma unroll
            for (int s = 0; s < 4; s++)
#pragma unroll
                for (int c = 0; c < NB; c++)
                    A(pos[s], k0 + c) = p[s][c];
        }
        __syncthreads();   // panel + pivot list visible to all warps

        int base = k0 + NB;
        int m = NLU - base;

        if (m > 0) {
            // ===== fused: apply row swaps + TRSM, per trailing column ============
            for (int j = base + tid; j < NLU; j += 256) {
#pragma unroll
                for (int k = 0; k < NB; k++) {
                    int qp = s_pivlist[k];
                    int kr = k0 + k;
                    if (qp != kr) {
                        float a0 = A(kr, j), b0 = A(qp, j);
                        A(kr, j) = b0; A(qp, j) = a0;
                    }
                }
                float u[NB];
#pragma unroll
                for (int rr = 0; rr < NB; rr++) {
                    float x = A(k0 + rr, j);
#pragma unroll
                    for (int t = 0; t < NB; t++)
                        if (t < rr) x -= A(k0 + rr, k0 + t) * u[t];
                    u[rr] = x;
                    A(k0 + rr, j) = x;
                }
            }
            __syncthreads();

            // ===== trailing GEMM: A22 -= L21 * U12 ===============================
            for (int sa = 0; sa < m; sa += 64)
            for (int sb = 0; sb < m; sb += 64) {
                int ia[4], jb[4];
                bool rok[4], cok[4];
#pragma unroll
                for (int a = 0; a < 4; a++) {
                    int i = base + sa + ty + 16 * a;
                    rok[a] = (i < NLU); ia[a] = rok[a] ? i : (NLU - 1);
                    int jj = base + sb + tx + 16 * a;
                    cok[a] = (jj < NLU); jb[a] = cok[a] ? jj : (NLU - 1);
                }
                float acc[4][4];
#pragma unroll
                for (int a = 0; a < 4; a++)
#pragma unroll
                for (int q = 0; q < 4; q++)
                    acc[a][q] = A(ia[a], jb[q]);
#pragma unroll
                for (int t = 0; t < NB; t++) {
                    float la[4], lb[4];
#pragma unroll
                    for (int a = 0; a < 4; a++) {
                        la[a] = A(ia[a], k0 + t);
                        lb[a] = A(k0 + t, jb[a]);
                    }
#pragma unroll
                    for (int a = 0; a < 4; a++)
#pragma unroll
                    for (int q = 0; q < 4; q++)
                        acc[a][q] -= la[a] * lb[q];
                }
#pragma unroll
                for (int a = 0; a < 4; a++)
#pragma unroll
                for (int q = 0; q < 4; q++)
                    if (rok[a] && cok[q]) A(ia[a], jb[q]) = acc[a][q];
            }
        }
    }

    if (tid == 0) {
        g_sign[cta] = t_sign;
        g_labs[cta] = t_logabs;
    }
}

// ---------------- kernel 4: combine ---------------------------------------------
__global__ void combine_kernel(float* __restrict__ out) {
    int b = blockIdx.x * 256 + threadIdx.x;
    if (b < BATCH) {
        out[b]         = g_sign[2 * b] * g_sign[2 * b + 1];
        out[BATCH + b] = g_logj[b] + g_labs[2 * b] + g_labs[2 * b + 1];
    }
}

// ---------------- launch ---------------------------------------------------------
extern "C" void kernel_launch(void* const* d_in, const int* in_sizes, int n_in,
                              void* d_out, int out_size) {
    const int*   n      = (const int*)d_in[0];
    const float* phi_up = (const float*)d_in[1];
    const float* phi_dn = (const float*)d_in[2];
    const float* v      = (const float*)d_in[3];
    float* out = (float*)d_out;

    const int LU_SMEM = NLU * 129 * (int)sizeof(float);   // 66048 B
    cudaFuncSetAttribute(lu_kernel, cudaFuncAttributeMaxDynamicSharedMemorySize, LU_SMEM);

    idx_kernel<<<BATCH, 256>>>(n);
    jastrow_kernel<<<BATCH / JB, 256>>>(n, v);
    lu_kernel<<<BATCH * 2, 256, LU_SMEM>>>(phi_up, phi_dn);
    combine_kernel<<<(BATCH + 255) / 256, 256>>>(out);
}